// round 12
// baseline (speedup 1.0000x reference)
#include <cuda_runtime.h>

// ---------------------------------------------------------------------------
// TexturedSoftPhongShader — R8: warp-converged active-sample worklist
//  Limiter (validated model): L1tex wavefront throughput. The 4 divergent
//  k-branches (~8 lanes each) are replaced by a converged ffs-driven loop:
//  iteration 1 runs ~32/32 lanes, later iterations only the rare extra
//  active samples. Scalar bary/texel loads and all lighting math issue once
//  at full warp width instead of 4x at 1/4 width.
// Inputs (metadata order):
//  0 texels (N,H,W,K,3) f32 | 1 bary (N,H,W,K,3) f32 | 2 zbuf (N,H,W,K) f32
//  3 dists (N,H,W,K) f32 | 4 verts (unused) | 5 vertex_normals (V,3) f32
//  6 gamma (N,27) f32 | 7 pix_to_face (N,H,W,K) i32 | 8 faces (F,3) i32
// Output: (N,H,W,4) f32
// ---------------------------------------------------------------------------

#define MAXF 70000

// 64B per face record (3 corners + pad): record never straddles a 128B line.
__device__ float4 g_fn[MAXF * 4];

__global__ __launch_bounds__(256)
void prep_kernel(const int* __restrict__ faces,
                 const float* __restrict__ vn, int FC) {
    int idx = blockIdx.x * blockDim.x + threadIdx.x;   // 0 .. 3F-1
    if (idx >= FC) return;
    int f      = idx / 3;
    int corner = idx - 3 * f;
    int v      = faces[idx];
    const float* nr = vn + 3 * v;
    g_fn[4 * f + corner] = make_float4(nr[0], nr[1], nr[2], 0.f);
}

// 4-way select without local-memory arrays (keeps everything in registers).
__device__ __forceinline__ int   sel4i(int k, int a, int b, int c, int d) {
    return (k < 2) ? ((k == 0) ? a : b) : ((k == 2) ? c : d);
}
__device__ __forceinline__ float sel4f(int k, float a, float b, float c, float d) {
    return (k < 2) ? ((k == 0) ? a : b) : ((k == 2) ? c : d);
}

__global__ __launch_bounds__(256, 4)
void shade_kernel(const float*  __restrict__ texels,
                  const float*  __restrict__ bary,
                  const float4* __restrict__ zbuf4,
                  const float4* __restrict__ dists4,
                  const int4*   __restrict__ p2f4,
                  const float*  __restrict__ gamma,
                  float4*       __restrict__ out,
                  int HW, int P) {
    const float A0C0   = 0.8862269254527580f;
    const float A1C1   = 1.7724538509055159f;
    const float A2C2   = 2.4270323670f;
    const float A2C2D0 = 0.7006239630f;

    const float EPS       = 1e-10f;
    const float INV_SIGMA = 1e4f;
    const float INV_GAMMA = 1e4f;
    const float INV_ZR    = 1.0f / 99.0f;

    // Folded per-image SH coefficients (flip, +0.8 bias, (3z^2-1) const folded)
    __shared__ float sC[9][3];
    int tid  = threadIdx.x;
    int pix0 = blockIdx.x * 256;
    if (tid < 3) {
        int c = tid;
        int n0 = pix0 / HW;
        const float* gp = gamma + n0 * 27 + c * 9;
        float g0 = gp[0] + 0.8f;
        float g6 = gp[6];
        sC[0][c] = A0C0 * g0 - A2C2D0 * g6;
        sC[1][c] = A1C1 * gp[1];
        sC[2][c] = A1C1 * gp[2];
        sC[3][c] = A1C1 * gp[3];
        sC[4][c] = A2C2 * gp[4];
        sC[5][c] = A2C2 * gp[5];
        sC[6][c] = 3.0f * A2C2D0 * g6;
        sC[7][c] = A2C2 * gp[7];
        sC[8][c] = A2C2 * 0.5f * gp[8];
    }
    __syncthreads();

    int pix = pix0 + tid;
    if (pix >= P) return;

    float4 z4 = zbuf4[pix];
    float4 d4 = dists4[pix];
    int4   f4 = p2f4[pix];

    int fv0 = f4.x, fv1 = f4.y, fv2 = f4.z, fv3 = f4.w;

    // z_inv + max (branchless)
    float zi0 = (fv0 >= 0) ? (100.0f - z4.x) * INV_ZR : 0.0f;
    float zi1 = (fv1 >= 0) ? (100.0f - z4.y) * INV_ZR : 0.0f;
    float zi2 = (fv2 >= 0) ? (100.0f - z4.z) * INV_ZR : 0.0f;
    float zi3 = (fv3 >= 0) ? (100.0f - z4.w) * INV_ZR : 0.0f;
    float zmax = fmaxf(fmaxf(fmaxf(zi0, zi1), fmaxf(zi2, zi3)), EPS);

    // Per-sample blend weights + alpha product, branchless.
    // exp underflow => w == 0 exactly (same as the f32 reference); skipped
    // contribution bounded by exp(-87)/1e-10 ~ 1e-28.
    float wsum = 0.f;
    float oma  = 1.f;
    unsigned mask = 0u;
    float w0, w1, w2, w3;
    {
        float p0 = (fv0 >= 0) ? __fdividef(1.0f, 1.0f + __expf(d4.x * INV_SIGMA)) : 0.0f;
        float p1 = (fv1 >= 0) ? __fdividef(1.0f, 1.0f + __expf(d4.y * INV_SIGMA)) : 0.0f;
        float p2 = (fv2 >= 0) ? __fdividef(1.0f, 1.0f + __expf(d4.z * INV_SIGMA)) : 0.0f;
        float p3 = (fv3 >= 0) ? __fdividef(1.0f, 1.0f + __expf(d4.w * INV_SIGMA)) : 0.0f;
        oma = (1.0f - p0) * (1.0f - p1) * (1.0f - p2) * (1.0f - p3);

        float a0 = (zi0 - zmax) * INV_GAMMA;
        float a1 = (zi1 - zmax) * INV_GAMMA;
        float a2 = (zi2 - zmax) * INV_GAMMA;
        float a3 = (zi3 - zmax) * INV_GAMMA;
        w0 = (a0 > -87.0f) ? p0 * __expf(a0) : 0.0f;
        w1 = (a1 > -87.0f) ? p1 * __expf(a1) : 0.0f;
        w2 = (a2 > -87.0f) ? p2 * __expf(a2) : 0.0f;
        w3 = (a3 > -87.0f) ? p3 * __expf(a3) : 0.0f;
        wsum = (w0 + w1) + (w2 + w3);
        if (w0 > 0.f) mask |= 1u;
        if (w1 > 0.f) mask |= 2u;
        if (w2 > 0.f) mask |= 4u;
        if (w3 > 0.f) mask |= 8u;
    }

    const float* tp = texels + (size_t)pix * 12;
    const float* bp = bary   + (size_t)pix * 12;

    // Converged worklist: every lane processes its next active sample in the
    // same instruction stream. Iteration 1 ~ full warp; later iterations only
    // the rare lanes with a 2nd/3rd live sample.
    float accR = 0.f, accG = 0.f, accB = 0.f;
    while (__any_sync(0xffffffffu, mask != 0u)) {
        if (mask) {
            int k = __ffs(mask) - 1;
            mask &= (mask - 1);
            int   face = sel4i(k, fv0, fv1, fv2, fv3);
            float wk   = sel4f(k, w0, w1, w2, w3);

            float b0 = bp[3 * k + 0], b1 = bp[3 * k + 1], b2 = bp[3 * k + 2];
            const float4* fp = g_fn + 4 * face;
            float4 v0 = fp[0];
            float4 v1 = fp[1];
            float4 v2 = fp[2];
            float mx = b0 * v0.x + b1 * v1.x + b2 * v2.x;
            float my = b0 * v0.y + b1 * v1.y + b2 * v2.y;
            float mz = b0 * v0.z + b1 * v1.z + b2 * v2.z;

            float pxy = mx * my;
            float pyz = my * mz;
            float pxz = mx * mz;
            float pzz = mz * mz;
            float pd  = fmaf(-my, my, mx * mx);

            float Lr = sC[0][0] + sC[1][0]*my + sC[2][0]*mz + sC[3][0]*mx
                     + sC[4][0]*pxy + sC[5][0]*pyz + sC[6][0]*pzz
                     + sC[7][0]*pxz + sC[8][0]*pd;
            float Lg = sC[0][1] + sC[1][1]*my + sC[2][1]*mz + sC[3][1]*mx
                     + sC[4][1]*pxy + sC[5][1]*pyz + sC[6][1]*pzz
                     + sC[7][1]*pxz + sC[8][1]*pd;
            float Lb = sC[0][2] + sC[1][2]*my + sC[2][2]*mz + sC[3][2]*mx
                     + sC[4][2]*pxy + sC[5][2]*pyz + sC[6][2]*pzz
                     + sC[7][2]*pxz + sC[8][2]*pd;

            accR = fmaf(wk, Lr * tp[3 * k + 0], accR);
            accG = fmaf(wk, Lg * tp[3 * k + 1], accG);
            accB = fmaf(wk, Lb * tp[3 * k + 2], accB);
        }
    }

    float delta  = fmaxf(__expf((EPS - zmax) * INV_GAMMA), EPS);
    float invden = __fdividef(1.0f, wsum + delta);
    float bg     = delta * invden;

    float4 o;
    o.x = fmaf(accR, invden, bg);
    o.y = fmaf(accG, invden, bg);
    o.z = fmaf(accB, invden, bg);
    o.w = 1.0f - oma;
    out[pix] = o;
}

extern "C" void kernel_launch(void* const* d_in, const int* in_sizes, int n_in,
                              void* d_out, int out_size) {
    const float* texels = (const float*)d_in[0];
    const float* bary   = (const float*)d_in[1];
    const float* zbuf   = (const float*)d_in[2];
    const float* dists  = (const float*)d_in[3];
    const float* vn     = (const float*)d_in[5];
    const float* gamma  = (const float*)d_in[6];
    const int*   p2f    = (const int*)d_in[7];
    const int*   faces  = (const int*)d_in[8];

    int FC = in_sizes[8];            // 3*F corners
    if (FC > MAXF * 3) FC = MAXF * 3;
    int P = in_sizes[2] / 4;
    int N = in_sizes[6] / 27;
    int HW = P / N;

    prep_kernel<<<(FC + 255) / 256, 256>>>(faces, vn, FC);
    shade_kernel<<<(P + 255) / 256, 256>>>(
        texels, bary,
        (const float4*)zbuf, (const float4*)dists,
        (const int4*)p2f, gamma, (float4*)d_out, HW, P);
}

// round 13
// speedup vs baseline: 1.1301x; 1.1301x over previous
#include <cuda_runtime.h>

// ---------------------------------------------------------------------------
// TexturedSoftPhongShader — R9: R6 structure (best) + float4-packed SH
// coefficient reads (27 scalar LDS -> 9 LDS.128 per active branch).
// Inputs (metadata order):
//  0 texels (N,H,W,K,3) f32 | 1 bary (N,H,W,K,3) f32 | 2 zbuf (N,H,W,K) f32
//  3 dists (N,H,W,K) f32 | 4 verts (unused) | 5 vertex_normals (V,3) f32
//  6 gamma (N,27) f32 | 7 pix_to_face (N,H,W,K) i32 | 8 faces (F,3) i32
// Output: (N,H,W,4) f32
// ---------------------------------------------------------------------------

#define MAXF 70000

// 64B per face record (3 corners + pad): record never straddles a 128B line.
__device__ float4 g_fn[MAXF * 4];

__global__ __launch_bounds__(256)
void prep_kernel(const int* __restrict__ faces,
                 const float* __restrict__ vn, int FC) {
    int idx = blockIdx.x * blockDim.x + threadIdx.x;   // 0 .. 3F-1
    if (idx >= FC) return;
    int f      = idx / 3;
    int corner = idx - 3 * f;
    int v      = faces[idx];
    const float* nr = vn + 3 * v;
    g_fn[4 * f + corner] = make_float4(nr[0], nr[1], nr[2], 0.f);
}

__global__ __launch_bounds__(256, 4)
void shade_kernel(const float*  __restrict__ texels,
                  const float*  __restrict__ bary,
                  const float4* __restrict__ zbuf4,
                  const float4* __restrict__ dists4,
                  const int4*   __restrict__ p2f4,
                  const float*  __restrict__ gamma,
                  float4*       __restrict__ out,
                  int HW, int P) {
    const float A0C0   = 0.8862269254527580f;
    const float A1C1   = 1.7724538509055159f;
    const float A2C2   = 2.4270323670f;
    const float A2C2D0 = 0.7006239630f;

    const float EPS       = 1e-10f;
    const float INV_SIGMA = 1e4f;
    const float INV_GAMMA = 1e4f;
    const float INV_ZR    = 1.0f / 99.0f;

    // Folded per-image SH coefficients, PADDED to float4 rows:
    // sC4[i] = (C_i^R, C_i^G, C_i^B, 0). One LDS.128 per basis term.
    __shared__ float4 sC4[9];
    int tid  = threadIdx.x;
    int pix0 = blockIdx.x * 256;
    if (tid < 3) {
        int c = tid;                       // channel
        int n0 = pix0 / HW;
        const float* gp = gamma + n0 * 27 + c * 9;
        float g0 = gp[0] + 0.8f;
        float g6 = gp[6];
        float* sCf = (float*)sC4;
        sCf[0 * 4 + c] = A0C0 * g0 - A2C2D0 * g6;
        sCf[1 * 4 + c] = A1C1 * gp[1];
        sCf[2 * 4 + c] = A1C1 * gp[2];
        sCf[3 * 4 + c] = A1C1 * gp[3];
        sCf[4 * 4 + c] = A2C2 * gp[4];
        sCf[5 * 4 + c] = A2C2 * gp[5];
        sCf[6 * 4 + c] = 3.0f * A2C2D0 * g6;
        sCf[7 * 4 + c] = A2C2 * gp[7];
        sCf[8 * 4 + c] = A2C2 * 0.5f * gp[8];
        sCf[0 * 4 + 3] = 0.f;              // pad lanes (any thread; benign)
    }
    __syncthreads();

    int pix = pix0 + tid;
    if (pix >= P) return;

    float4 z4 = zbuf4[pix];
    float4 d4 = dists4[pix];
    int4   f4 = p2f4[pix];
    float zv[4] = {z4.x, z4.y, z4.z, z4.w};
    float dv[4] = {d4.x, d4.y, d4.z, d4.w};
    int   fv[4] = {f4.x, f4.y, f4.z, f4.w};

    // Pass 1: z_inv + max
    float zi[4];
    float zmax = EPS;
#pragma unroll
    for (int k = 0; k < 4; k++) {
        bool m = fv[k] >= 0;
        zi[k] = m ? (100.0f - zv[k]) * INV_ZR : 0.0f;
        zmax = fmaxf(zmax, zi[k]);
    }

    const float* tp = texels + (size_t)pix * 12;
    const float* bp = bary   + (size_t)pix * 12;

    // Pass 2: alpha product for all valid samples; gather+lighting ONLY where
    // the blend weight is representable (exp underflow => exact 0 in the
    // reference too; skipped term bounded by ~1e-28).
    float accR = 0.f, accG = 0.f, accB = 0.f;
    float wsum = 0.f;
    float oma  = 1.f;
#pragma unroll
    for (int k = 0; k < 4; k++) {
        if (fv[k] >= 0) {
            float prob = __fdividef(1.0f, 1.0f + __expf(dv[k] * INV_SIGMA));
            oma *= (1.0f - prob);
            float arg = (zi[k] - zmax) * INV_GAMMA;
            if (arg > -87.0f) {
                float w = prob * __expf(arg);
                wsum += w;

                float b0 = bp[3 * k + 0], b1 = bp[3 * k + 1], b2 = bp[3 * k + 2];
                const float4* fp = g_fn + 4 * fv[k];
                float4 v0 = fp[0];
                float4 v1 = fp[1];
                float4 v2 = fp[2];
                float mx = b0 * v0.x + b1 * v1.x + b2 * v2.x;
                float my = b0 * v0.y + b1 * v1.y + b2 * v2.y;
                float mz = b0 * v0.z + b1 * v1.z + b2 * v2.z;

                float pxy = mx * my;
                float pyz = my * mz;
                float pxz = mx * mz;
                float pzz = mz * mz;
                float pd  = fmaf(-my, my, mx * mx);

                // 9 x LDS.128, channels advance together.
                float4 q;
                q = sC4[0];
                float Lr = q.x,              Lg = q.y,              Lb = q.z;
                q = sC4[1];
                Lr = fmaf(q.x, my,  Lr); Lg = fmaf(q.y, my,  Lg); Lb = fmaf(q.z, my,  Lb);
                q = sC4[2];
                Lr = fmaf(q.x, mz,  Lr); Lg = fmaf(q.y, mz,  Lg); Lb = fmaf(q.z, mz,  Lb);
                q = sC4[3];
                Lr = fmaf(q.x, mx,  Lr); Lg = fmaf(q.y, mx,  Lg); Lb = fmaf(q.z, mx,  Lb);
                q = sC4[4];
                Lr = fmaf(q.x, pxy, Lr); Lg = fmaf(q.y, pxy, Lg); Lb = fmaf(q.z, pxy, Lb);
                q = sC4[5];
                Lr = fmaf(q.x, pyz, Lr); Lg = fmaf(q.y, pyz, Lg); Lb = fmaf(q.z, pyz, Lb);
                q = sC4[6];
                Lr = fmaf(q.x, pzz, Lr); Lg = fmaf(q.y, pzz, Lg); Lb = fmaf(q.z, pzz, Lb);
                q = sC4[7];
                Lr = fmaf(q.x, pxz, Lr); Lg = fmaf(q.y, pxz, Lg); Lb = fmaf(q.z, pxz, Lb);
                q = sC4[8];
                Lr = fmaf(q.x, pd,  Lr); Lg = fmaf(q.y, pd,  Lg); Lb = fmaf(q.z, pd,  Lb);

                accR = fmaf(w, Lr * tp[3 * k + 0], accR);
                accG = fmaf(w, Lg * tp[3 * k + 1], accG);
                accB = fmaf(w, Lb * tp[3 * k + 2], accB);
            }
        }
    }

    float delta  = fmaxf(__expf((EPS - zmax) * INV_GAMMA), EPS);
    float invden = __fdividef(1.0f, wsum + delta);
    float bg     = delta * invden;

    float4 o;
    o.x = fmaf(accR, invden, bg);
    o.y = fmaf(accG, invden, bg);
    o.z = fmaf(accB, invden, bg);
    o.w = 1.0f - oma;
    out[pix] = o;
}

extern "C" void kernel_launch(void* const* d_in, const int* in_sizes, int n_in,
                              void* d_out, int out_size) {
    const float* texels = (const float*)d_in[0];
    const float* bary   = (const float*)d_in[1];
    const float* zbuf   = (const float*)d_in[2];
    const float* dists  = (const float*)d_in[3];
    const float* vn     = (const float*)d_in[5];
    const float* gamma  = (const float*)d_in[6];
    const int*   p2f    = (const int*)d_in[7];
    const int*   faces  = (const int*)d_in[8];

    int FC = in_sizes[8];            // 3*F corners
    if (FC > MAXF * 3) FC = MAXF * 3;
    int P = in_sizes[2] / 4;
    int N = in_sizes[6] / 27;
    int HW = P / N;

    prep_kernel<<<(FC + 255) / 256, 256>>>(faces, vn, FC);
    shade_kernel<<<(P + 255) / 256, 256>>>(
        texels, bary,
        (const float4*)zbuf, (const float4*)dists,
        (const int4*)p2f, gamma, (float4*)d_out, HW, P);
}